// round 5
// baseline (speedup 1.0000x reference)
#include <cuda_runtime.h>
#include <cstdint>

// image2patch: input (32,8,256,256) f32 -> output (256, 3969, 64) f32
// PSIZE=8, STRIDE=4, WINDOW=249, cur = 0,4,...,248 (63 positions per dim).
// out[img, p, di*8+dj] = in[img, (p/63)*4 + di, (p%63)*4 + dj]
//
// One thread = one patch-row: 8 contiguous floats in BOTH input and output,
// both 16B-aligned -> 2x LDG.128 + 2x STG.128, fully coalesced stores.

#define IMG_PIXELS   65536   // 256*256
#define IMG_W        256
#define PATCHES      3969    // 63*63
#define ROWS_PER_IMG 31752   // 3969 * 8
#define GRID_DIM     63

__global__ __launch_bounds__(256)
void image2patch_kernel(const float* __restrict__ in,
                        float4* __restrict__ out,
                        int total_rows)
{
    int t = blockIdx.x * blockDim.x + threadIdx.x;
    if (t >= total_rows) return;

    int img = t / ROWS_PER_IMG;
    int rem = t - img * ROWS_PER_IMG;
    int p   = rem >> 3;          // patch index within image
    int di  = rem & 7;           // row within patch
    int row = p / GRID_DIM;
    int col = p - row * GRID_DIM;

    const float4* src = reinterpret_cast<const float4*>(
        in + (size_t)img * IMG_PIXELS + (row * 4 + di) * IMG_W + col * 4);

    float4 a = src[0];
    float4 b = src[1];

    size_t o = (size_t)t * 2;
    out[o]     = a;
    out[o + 1] = b;
}

extern "C" void kernel_launch(void* const* d_in, const int* in_sizes, int n_in,
                              void* d_out, int out_size)
{
    const float* in = (const float*)d_in[0];
    float4* out = (float4*)d_out;

    int n_images   = in_sizes[0] / IMG_PIXELS;     // 256
    int total_rows = n_images * ROWS_PER_IMG;      // 8,128,512

    int threads = 256;
    int blocks  = (total_rows + threads - 1) / threads;
    image2patch_kernel<<<blocks, threads>>>(in, out, total_rows);
}

// round 6
// speedup vs baseline: 1.4312x; 1.4312x over previous
#include <cuda_runtime.h>
#include <cstdint>

// image2patch: in (32,8,256,256) f32 -> out (256, 3969, 64) f32
// PSIZE=8, STRIDE=4, 63x63 patch grid per image.
//
// R5 insight: old mapping was L1-bound (93.9%) from divergent loads
// (consecutive lanes read addresses 1024B apart). Fix: smem staging.
//
// One block per (img, patch_row pr):
//   - input rows [4*pr, 4*pr+8) are 512 CONTIGUOUS float4 in gmem -> smem (coalesced)
//   - output for (img, pr, all 63 cols) is 1008 CONTIGUOUS float4 in gmem (coalesced)
//   - smem gather: padded row stride 66 float4 (== 2 mod 8) => conflict-free LDS.128
//
// out float4 index within region: f = col*16 + di*2 + h   (h = dj/4)
//   <-> smem float4 [di*66 + col + h]

#define IMG_F4       16384   // 256*256/4
#define ROW_F4       64      // 256/4
#define GRID_DIM     63
#define SMEM_STRIDE  66      // 64 + 2 pad (stride % 8 == 2 -> bank-conflict-free gather)
#define OUT_F4       1008    // 63 patches * 16 float4

__global__ __launch_bounds__(256)
void image2patch_kernel(const float4* __restrict__ in,
                        float4* __restrict__ out)
{
    __shared__ float4 s[8 * SMEM_STRIDE];

    int b   = blockIdx.x;
    int img = b / GRID_DIM;
    int pr  = b - img * GRID_DIM;
    int tid = threadIdx.x;

    // Stage 1: copy 8 input rows (512 contiguous float4) into padded smem.
    const float4* src = in + (size_t)img * IMG_F4 + (size_t)pr * 4 * ROW_F4;
#pragma unroll
    for (int k = 0; k < 2; k++) {
        int g = tid + k * 256;             // 0..511
        int r = g >> 6;                    // input row 0..7
        int c = g & 63;                    // float4 col 0..63
        s[r * SMEM_STRIDE + c] = __ldg(&src[g]);
    }
    __syncthreads();

    // Stage 2: write 1008 contiguous output float4, gathered from smem.
    float4* dst = out + (size_t)b * OUT_F4;
#pragma unroll
    for (int it = 0; it < 4; it++) {
        int f = tid + it * 256;
        if (f < OUT_F4) {
            int col = f >> 4;              // patch col 0..62
            int q   = f & 15;
            int di  = q >> 1;              // row within patch 0..7
            int h   = q & 1;               // which half of the 8-float patch row
            __stcs(&dst[f], s[di * SMEM_STRIDE + col + h]);
        }
    }
}

extern "C" void kernel_launch(void* const* d_in, const int* in_sizes, int n_in,
                              void* d_out, int out_size)
{
    const float4* in = (const float4*)d_in[0];
    float4* out = (float4*)d_out;

    int n_images = in_sizes[0] / (IMG_F4 * 4);   // 256
    int blocks   = n_images * GRID_DIM;          // 16128

    image2patch_kernel<<<blocks, 256>>>(in, out);
}